// round 11
// baseline (speedup 1.0000x reference)
#include <cuda_runtime.h>
#include <cuda_fp16.h>
#include <cstdint>
#include <cstddef>

#define BATCH 8192
#define NREC  1024
#define HID   2048

// All tiles operate on u32 = half2 (k-pair packed) words.
#define SA 36       // A smem row stride (u32)
#define SB 136      // B smem row stride (u32)
#define A_TILE (128 * SA)    // 4608 u32
#define B_TILE (32 * SB)     // 4352 u32
#define ST (A_TILE + B_TILE) // 8960 u32 per stage
#define SMEM_B (3 * ST * (int)sizeof(uint32_t))    // 107520 -> 2 CTAs/SM

extern __shared__ uint32_t smem[];

// ---- packed scratch (half2 words) ----
__device__ uint32_t g_PU[(size_t)BATCH * (NREC / 2)];
__device__ uint32_t g_PB[2u * (NREC / 2) * HID];             // [Bre|Bim], [k2][n] n-permuted
__device__ uint32_t g_PC[(size_t)HID * NREC];                // [Cre;-Cim], [k2=2048][n] n-permuted
__device__ uint32_t g_PXre[(size_t)BATCH * (HID / 2)];
__device__ uint32_t g_PXim[(size_t)BATCH * (HID / 2)];

__device__ __forceinline__ void mma16(float* d, const uint32_t* a, uint32_t b0, uint32_t b1) {
    asm volatile(
        "mma.sync.aligned.m16n8k16.row.col.f32.f16.f16.f32 "
        "{%0,%1,%2,%3}, {%4,%5,%6,%7}, {%8,%9}, {%0,%1,%2,%3};\n"
        : "+f"(d[0]), "+f"(d[1]), "+f"(d[2]), "+f"(d[3])
        : "r"(a[0]), "r"(a[1]), "r"(a[2]), "r"(a[3]), "r"(b0), "r"(b1));
}
__device__ __forceinline__ void ldsm4(uint32_t* r, uint32_t addr) {
    asm volatile("ldmatrix.sync.aligned.m8n8.x4.shared.b16 {%0,%1,%2,%3}, [%4];"
        : "=r"(r[0]), "=r"(r[1]), "=r"(r[2]), "=r"(r[3]) : "r"(addr));
}
__device__ __forceinline__ void cp16(void* s, const void* g) {
    uint32_t sa = (uint32_t)__cvta_generic_to_shared(s);
    asm volatile("cp.async.cg.shared.global [%0], [%1], 16;\n" :: "r"(sa), "l"(g));
}
__device__ __forceinline__ void cp_commit() { asm volatile("cp.async.commit_group;\n"); }
__device__ __forceinline__ void cp_wait0()  { asm volatile("cp.async.wait_group 0;\n"); }
__device__ __forceinline__ void cp_wait1()  { asm volatile("cp.async.wait_group 1;\n"); }

__device__ __forceinline__ uint32_t packh2(float x, float y) {
    __half2 h = __floats2half2_rn(x, y);
    return *(uint32_t*)&h;
}
__device__ __forceinline__ uint32_t s2u(const void* p) {
    return (uint32_t)__cvta_generic_to_shared(p);
}

// ---- prep weights: pack k-pairs into half2, permute n within 32-blocks, negate Cim.
__global__ __launch_bounds__(256) void prep_w(
    const float* __restrict__ B0, const float* __restrict__ B1,
    const float* __restrict__ C0, const float* __restrict__ C1,
    uint32_t* __restrict__ PB, uint32_t* __restrict__ PC)
{
    const int idx = blockIdx.x * 256 + threadIdx.x;
    const int z = blockIdx.y;
    const float* src; uint32_t* dst; int sh; float sign = 1.f;
    if (z == 0)      { src = B0; dst = PB;                            sh = 11; }
    else if (z == 1) { src = B1; dst = PB + (NREC / 2) * HID;         sh = 11; }
    else if (z == 2) { src = C0; dst = PC;                            sh = 10; }
    else             { src = C1; dst = PC + (size_t)(HID / 2) * NREC; sh = 10; sign = -1.f; }
    const int N = 1 << sh;
    const int k2 = idx >> sh, l = idx & (N - 1);
    const int base = l & ~31, p = l & 31;
    const int nt = base + ((p & 3) * 8) + (p >> 2);
    float v0 = sign * src[((size_t)(2 * k2) << sh) + nt];
    float v1 = sign * src[((size_t)(2 * k2 + 1) << sh) + nt];
    dst[idx] = packh2(v0, v1);
}

__global__ __launch_bounds__(256) void prep_u(const float* __restrict__ U,
                                              uint32_t* __restrict__ PU)
{
    const int idx = blockIdx.x * 256 + threadIdx.x;
    const float2 v = *(const float2*)(U + 2 * (size_t)idx);
    PU[idx] = packh2(v.x, v.y);
}

// fragment load helper: one ks-group (4 ldsm4 + 2 LDS.128)
#define LOAD_FRAGS(buf, ksv)                                                        \
    do {                                                                            \
        const int _kk = (ksv) * 8;                                                  \
        _Pragma("unroll")                                                           \
        for (int _i = 0; _i < 4; _i++)                                              \
            ldsm4(af[buf][_i], aBase + (uint32_t)(((_i * 16) * SA + _kk) << 2));    \
        uint4 _v0 = *(const uint4*)(b + (_kk + t) * SB + wn + 4 * g);               \
        uint4 _v1 = *(const uint4*)(b + (_kk + t + 4) * SB + wn + 4 * g);           \
        bf[buf][0] = _v0.x; bf[buf][1] = _v0.y; bf[buf][2] = _v0.z; bf[buf][3] = _v0.w; \
        bf[buf][4] = _v1.x; bf[buf][5] = _v1.y; bf[buf][6] = _v1.z; bf[buf][7] = _v1.w; \
    } while (0)

#define DO_MMAS(buf)                                                                \
    do {                                                                            \
        _Pragma("unroll")                                                           \
        for (int _i = 0; _i < 4; _i++)                                              \
            _Pragma("unroll")                                                       \
            for (int _j = 0; _j < 4; _j++)                                          \
                mma16(acc[_i][_j], af[buf][_i], bf[buf][_j], bf[buf][4 + _j]);      \
    } while (0)

// =============================================================================
// GEMM1: T = U @ B{re|im} (z selects); X{re|im} = f(S, T); emits fp32 + packed X.
// block 128x128, 256 thr, warp 64x32, 3 stages, 2 CTAs/SM, frag double-buffering
// =============================================================================
__global__ __launch_bounds__(256, 2) void lru_g1(
    const uint32_t* __restrict__ PU,
    const uint32_t* __restrict__ PB,
    const float* __restrict__ Sre, const float* __restrict__ Sim,
    const float* __restrict__ nu,  const float* __restrict__ theta,
    const float* __restrict__ gam,
    float* __restrict__ Xre, float* __restrict__ Xim,
    uint32_t* __restrict__ PXre, uint32_t* __restrict__ PXim)
{
    const int n0 = blockIdx.x * 128;     // HID
    const int m0 = blockIdx.y * 128;     // BATCH
    const int z  = blockIdx.z;
    const uint32_t* __restrict__ Bmat = PB + (size_t)z * (NREC / 2) * HID;

    const int tid = threadIdx.x, warp = tid >> 5, lane = tid & 31;
    const int g = lane >> 2, t = lane & 3;
    const int wm = (warp >> 2) * 64, wn = (warp & 3) * 32;
    const int lm = lane >> 3;
    const int arow = wm + (lm & 1) * 8 + (lane & 7);
    const int acol = (lm >> 1) * 4;

    float acc[4][4][4];
    #pragma unroll
    for (int i = 0; i < 4; i++)
        #pragma unroll
        for (int j = 0; j < 4; j++)
            #pragma unroll
            for (int r = 0; r < 4; r++) acc[i][j][r] = 0.f;

    auto loadStage = [&](int s, int kt) {
        uint32_t* a = smem + s * ST;
        uint32_t* b = a + A_TILE;
        const int k2 = kt * 32;
        #pragma unroll
        for (int i = 0; i < 4; i++) {
            int c = tid + i * 256;
            int row = c >> 3, cc = (c & 7) * 4;
            cp16(a + row * SA + cc, PU + (size_t)(m0 + row) * (NREC / 2) + k2 + cc);
        }
        #pragma unroll
        for (int i = 0; i < 4; i++) {
            int c = tid + i * 256;
            int row = c >> 5, cc = (c & 31) * 4;
            cp16(b + row * SB + cc, Bmat + (size_t)(k2 + row) * HID + n0 + cc);
        }
    };

    const int NKT = (NREC / 2) / 32;   // 16
    loadStage(0, 0); cp_commit();
    loadStage(1, 1); cp_commit();

    for (int kt = 0; kt < NKT; kt++) {
        if (kt + 2 < NKT) cp_wait1(); else cp_wait0();
        __syncthreads();
        if (kt + 2 < NKT) { loadStage((kt + 2) % 3, kt + 2); cp_commit(); }

        const int s = kt % 3;
        const uint32_t* a = smem + s * ST;
        const uint32_t* b = a + A_TILE;
        const uint32_t aBase = s2u(a) + (uint32_t)((arow * SA + acol) << 2);

        uint32_t af[2][4][4];
        uint32_t bf[2][8];
        LOAD_FRAGS(0, 0);
        #pragma unroll
        for (int ks = 0; ks < 4; ks++) {
            const int cur = ks & 1;
            if (ks < 3) LOAD_FRAGS(cur ^ 1, ks + 1);
            DO_MMAS(cur);
        }
    }

    // lambda/gamma tables for this block's 128 true H-columns
    float* sLr = (float*)smem;
    float* sLi = sLr + 128;
    float* sG  = sLr + 256;
    __syncthreads();
    if (tid < 128) {
        int h = n0 + tid;
        float e = expf(-expf(nu[h]));
        float th = theta[h];
        sLr[tid] = e * cosf(th);
        sLi[tid] = e * sinf(th);
        sG[tid]  = gam[h];
    }
    __syncthreads();

    float* __restrict__ Xout = z ? Xim : Xre;
    uint32_t* __restrict__ PXout = z ? PXim : PXre;
    #pragma unroll
    for (int i = 0; i < 4; i++) {
        int r0 = m0 + wm + i * 16 + g;
        #pragma unroll
        for (int j = 0; j < 4; j++) {
            int cl = wn + j * 8 + 2 * t;
            float lr0 = sLr[cl],     li0 = sLi[cl],     g0 = sG[cl];
            float lr1 = sLr[cl + 1], li1 = sLi[cl + 1], g1 = sG[cl + 1];
            #pragma unroll
            for (int rr = 0; rr < 2; rr++) {
                int r = r0 + rr * 8;
                size_t off = (size_t)r * HID + n0 + cl;
                float2 sre = *(const float2*)(Sre + off);
                float2 sim = *(const float2*)(Sim + off);
                float t0 = acc[i][j][rr * 2 + 0], t1 = acc[i][j][rr * 2 + 1];
                float2 o;
                if (z == 0) {
                    o.x = sre.x * lr0 - sim.x * li0 + g0 * t0;
                    o.y = sre.y * lr1 - sim.y * li1 + g1 * t1;
                } else {
                    o.x = sre.x * li0 + sim.x * lr0 + g0 * t0;
                    o.y = sre.y * li1 + sim.y * lr1 + g1 * t1;
                }
                *(float2*)(Xout + off) = o;
                PXout[(size_t)r * (HID / 2) + (n0 + cl) / 2] = packh2(o.x, o.y);
            }
        }
    }
}

// =============================================================================
// GEMM2: Y = [Xre|Xim] @ [Cre;-Cim] + D*U   (K = 4096 halfs = 2048 u32)
// block 128x128, 256 thr, warp 64x32, 3 stages, 2 CTAs/SM, frag double-buffering
// =============================================================================
__global__ __launch_bounds__(256, 2) void lru_g2(
    const uint32_t* __restrict__ PXre, const uint32_t* __restrict__ PXim,
    const uint32_t* __restrict__ PC,
    const float* __restrict__ Dv,  const float* __restrict__ U,
    float* __restrict__ Y)
{
    const int n0 = blockIdx.x * 128;     // NREC
    const int m0 = blockIdx.y * 128;     // BATCH
    const int tid = threadIdx.x, warp = tid >> 5, lane = tid & 31;
    const int g = lane >> 2, t = lane & 3;
    const int wm = (warp >> 2) * 64, wn = (warp & 3) * 32;
    const int lm = lane >> 3;
    const int arow = wm + (lm & 1) * 8 + (lane & 7);
    const int acol = (lm >> 1) * 4;

    float acc[4][4][4];
    #pragma unroll
    for (int i = 0; i < 4; i++)
        #pragma unroll
        for (int j = 0; j < 4; j++)
            #pragma unroll
            for (int r = 0; r < 4; r++) acc[i][j][r] = 0.f;

    auto loadStage = [&](int s, int kt) {
        uint32_t* a = smem + s * ST;
        uint32_t* b = a + A_TILE;
        const int k2 = kt * 32;
        const uint32_t* Asrc = (k2 < HID / 2) ? PXre : PXim;
        const int ka = k2 & (HID / 2 - 1);
        #pragma unroll
        for (int i = 0; i < 4; i++) {
            int c = tid + i * 256;
            int row = c >> 3, cc = (c & 7) * 4;
            cp16(a + row * SA + cc, Asrc + (size_t)(m0 + row) * (HID / 2) + ka + cc);
        }
        #pragma unroll
        for (int i = 0; i < 4; i++) {
            int c = tid + i * 256;
            int row = c >> 5, cc = (c & 31) * 4;
            cp16(b + row * SB + cc, PC + (size_t)(k2 + row) * NREC + n0 + cc);
        }
    };

    const int NKT = 2048 / 32;    // 64
    loadStage(0, 0); cp_commit();
    loadStage(1, 1); cp_commit();

    for (int kt = 0; kt < NKT; kt++) {
        if (kt + 2 < NKT) cp_wait1(); else cp_wait0();
        __syncthreads();
        if (kt + 2 < NKT) { loadStage((kt + 2) % 3, kt + 2); cp_commit(); }

        const int s = kt % 3;
        const uint32_t* a = smem + s * ST;
        const uint32_t* b = a + A_TILE;
        const uint32_t aBase = s2u(a) + (uint32_t)((arow * SA + acol) << 2);

        uint32_t af[2][4][4];
        uint32_t bf[2][8];
        LOAD_FRAGS(0, 0);
        #pragma unroll
        for (int ks = 0; ks < 4; ks++) {
            const int cur = ks & 1;
            if (ks < 3) LOAD_FRAGS(cur ^ 1, ks + 1);
            DO_MMAS(cur);
        }
    }

    #pragma unroll
    for (int i = 0; i < 4; i++) {
        int r0 = m0 + wm + i * 16 + g;
        #pragma unroll
        for (int j = 0; j < 4; j++) {
            int cl = wn + j * 8 + 2 * t;
            int c  = n0 + cl;
            float d0 = Dv[c], d1 = Dv[c + 1];
            #pragma unroll
            for (int rr = 0; rr < 2; rr++) {
                int r = r0 + rr * 8;
                size_t off = (size_t)r * NREC + c;
                float2 u = *(const float2*)(U + off);
                float2 o;
                o.x = acc[i][j][rr * 2 + 0] + d0 * u.x;
                o.y = acc[i][j][rr * 2 + 1] + d1 * u.y;
                *(float2*)(Y + off) = o;
            }
        }
    }
}

// =============================================================================
extern "C" void kernel_launch(void* const* d_in, const int* in_sizes, int n_in,
                              void* d_out, int out_size)
{
    const float* U   = (const float*)d_in[0];
    const float* Sre = (const float*)d_in[1];
    const float* Sim = (const float*)d_in[2];
    const float* Bre = (const float*)d_in[3];
    const float* Bim = (const float*)d_in[4];
    const float* Cre = (const float*)d_in[5];
    const float* Cim = (const float*)d_in[6];
    const float* Dv  = (const float*)d_in[7];
    const float* nu  = (const float*)d_in[8];
    const float* th  = (const float*)d_in[9];
    const float* gm  = (const float*)d_in[10];

    float* Y   = (float*)d_out;
    float* Xre = Y + (size_t)BATCH * NREC;
    float* Xim = Xre + (size_t)BATCH * HID;

    uint32_t *PU, *PB, *PC, *PXre, *PXim;
    cudaGetSymbolAddress((void**)&PU, g_PU);
    cudaGetSymbolAddress((void**)&PB, g_PB);
    cudaGetSymbolAddress((void**)&PC, g_PC);
    cudaGetSymbolAddress((void**)&PXre, g_PXre);
    cudaGetSymbolAddress((void**)&PXim, g_PXim);

    dim3 gw((NREC / 2) * HID / 256, 4);
    prep_w<<<gw, 256>>>(Bre, Bim, Cre, Cim, PB, PC);
    prep_u<<<BATCH * (NREC / 2) / 256, 256>>>(U, PU);

    cudaFuncSetAttribute(lru_g1, cudaFuncAttributeMaxDynamicSharedMemorySize, SMEM_B);
    cudaFuncSetAttribute(lru_g2, cudaFuncAttributeMaxDynamicSharedMemorySize, SMEM_B);

    dim3 g1(HID / 128, BATCH / 128, 2);    // 16 x 64 x 2
    lru_g1<<<g1, 256, SMEM_B>>>(PU, PB, Sre, Sim, nu, th, gm, Xre, Xim, PXre, PXim);

    dim3 g2(NREC / 128, BATCH / 128);      // 8 x 64
    lru_g2<<<g2, 256, SMEM_B>>>(PXre, PXim, PC, Dv, U, Y);
}

// round 12
// speedup vs baseline: 1.0160x; 1.0160x over previous
#include <cuda_runtime.h>
#include <cuda_fp16.h>
#include <cstdint>
#include <cstddef>

#define BATCH 8192
#define NREC  1024
#define HID   2048

// All tiles operate on u32 = half2 (k-pair packed) words.
#define SA 36       // A smem row stride (u32)
#define SB 136      // B smem row stride (u32)
#define A_TILE (128 * SA)    // 4608 u32
#define B_TILE (32 * SB)     // 4352 u32
#define ST (A_TILE + B_TILE) // 8960 u32 per stage
#define SMEM_B (3 * ST * (int)sizeof(uint32_t))    // 107520 -> 2 CTAs/SM

extern __shared__ uint32_t smem[];

// ---- packed scratch (half2 words) ----
__device__ uint32_t g_PU[(size_t)BATCH * (NREC / 2)];
__device__ uint32_t g_PB[2u * (NREC / 2) * HID];             // [Bre|Bim], [k2][n] n-permuted
__device__ uint32_t g_PC[(size_t)HID * NREC];                // [Cre;-Cim], [k2=2048][n] n-permuted
__device__ uint32_t g_PXre[(size_t)BATCH * (HID / 2)];
__device__ uint32_t g_PXim[(size_t)BATCH * (HID / 2)];

__device__ __forceinline__ void mma16(float* d, const uint32_t* a, uint32_t b0, uint32_t b1) {
    asm volatile(
        "mma.sync.aligned.m16n8k16.row.col.f32.f16.f16.f32 "
        "{%0,%1,%2,%3}, {%4,%5,%6,%7}, {%8,%9}, {%0,%1,%2,%3};\n"
        : "+f"(d[0]), "+f"(d[1]), "+f"(d[2]), "+f"(d[3])
        : "r"(a[0]), "r"(a[1]), "r"(a[2]), "r"(a[3]), "r"(b0), "r"(b1));
}
__device__ __forceinline__ void ldsm4(uint32_t* r, uint32_t addr) {
    asm volatile("ldmatrix.sync.aligned.m8n8.x4.shared.b16 {%0,%1,%2,%3}, [%4];"
        : "=r"(r[0]), "=r"(r[1]), "=r"(r[2]), "=r"(r[3]) : "r"(addr));
}
__device__ __forceinline__ void cp16(void* s, const void* g) {
    uint32_t sa = (uint32_t)__cvta_generic_to_shared(s);
    asm volatile("cp.async.cg.shared.global [%0], [%1], 16;\n" :: "r"(sa), "l"(g));
}
__device__ __forceinline__ void cp_commit() { asm volatile("cp.async.commit_group;\n"); }
__device__ __forceinline__ void cp_wait0()  { asm volatile("cp.async.wait_group 0;\n"); }
__device__ __forceinline__ void cp_wait1()  { asm volatile("cp.async.wait_group 1;\n"); }

__device__ __forceinline__ uint32_t packh2(float x, float y) {
    __half2 h = __floats2half2_rn(x, y);
    return *(uint32_t*)&h;
}
__device__ __forceinline__ uint32_t s2u(const void* p) {
    return (uint32_t)__cvta_generic_to_shared(p);
}

// ---- prep weights: pack k-pairs into half2, permute n within 32-blocks, negate Cim.
__global__ __launch_bounds__(256) void prep_w(
    const float* __restrict__ B0, const float* __restrict__ B1,
    const float* __restrict__ C0, const float* __restrict__ C1,
    uint32_t* __restrict__ PB, uint32_t* __restrict__ PC)
{
    const int idx = blockIdx.x * 256 + threadIdx.x;
    const int z = blockIdx.y;
    const float* src; uint32_t* dst; int sh; float sign = 1.f;
    if (z == 0)      { src = B0; dst = PB;                            sh = 11; }
    else if (z == 1) { src = B1; dst = PB + (NREC / 2) * HID;         sh = 11; }
    else if (z == 2) { src = C0; dst = PC;                            sh = 10; }
    else             { src = C1; dst = PC + (size_t)(HID / 2) * NREC; sh = 10; sign = -1.f; }
    const int N = 1 << sh;
    const int k2 = idx >> sh, l = idx & (N - 1);
    const int base = l & ~31, p = l & 31;
    const int nt = base + ((p & 3) * 8) + (p >> 2);
    float v0 = sign * src[((size_t)(2 * k2) << sh) + nt];
    float v1 = sign * src[((size_t)(2 * k2 + 1) << sh) + nt];
    dst[idx] = packh2(v0, v1);
}

__global__ __launch_bounds__(256) void prep_u(const float* __restrict__ U,
                                              uint32_t* __restrict__ PU)
{
    const int idx = blockIdx.x * 256 + threadIdx.x;
    const float2 v = *(const float2*)(U + 2 * (size_t)idx);
    PU[idx] = packh2(v.x, v.y);
}

// one ks-group for warp tile 64x64: 4 ldsm4 (A) + 4 LDS.128 (B), then 32 MMAs
#define KSTEP(ksv)                                                                  \
    do {                                                                            \
        const int _kk = (ksv) * 8;                                                  \
        uint32_t af[4][4];                                                          \
        _Pragma("unroll")                                                           \
        for (int _i = 0; _i < 4; _i++)                                              \
            ldsm4(af[_i], aBase + (uint32_t)(((_i * 16) * SA + _kk) << 2));         \
        uint4 _v0 = *(const uint4*)(b + (_kk + t) * SB + wn + 4 * g);               \
        uint4 _v1 = *(const uint4*)(b + (_kk + t + 4) * SB + wn + 4 * g);           \
        uint4 _v2 = *(const uint4*)(b + (_kk + t) * SB + wn + 32 + 4 * g);          \
        uint4 _v3 = *(const uint4*)(b + (_kk + t + 4) * SB + wn + 32 + 4 * g);      \
        uint32_t b0[8] = {_v0.x, _v0.y, _v0.z, _v0.w, _v2.x, _v2.y, _v2.z, _v2.w};  \
        uint32_t b1[8] = {_v1.x, _v1.y, _v1.z, _v1.w, _v3.x, _v3.y, _v3.z, _v3.w};  \
        _Pragma("unroll")                                                           \
        for (int _i = 0; _i < 4; _i++)                                              \
            _Pragma("unroll")                                                       \
            for (int _j = 0; _j < 8; _j++)                                          \
                mma16(acc[_i][_j], af[_i], b0[_j], b1[_j]);                         \
    } while (0)

// =============================================================================
// GEMM1: T = U @ B{re|im} (z selects); X{re|im} = f(S, T); emits fp32 + packed X.
// block 128x128, 128 thr, 4 warps (2M x 2N), warp 64x64, 3 stages, 2 CTAs/SM
// =============================================================================
__global__ __launch_bounds__(128, 2) void lru_g1(
    const uint32_t* __restrict__ PU,
    const uint32_t* __restrict__ PB,
    const float* __restrict__ Sre, const float* __restrict__ Sim,
    const float* __restrict__ nu,  const float* __restrict__ theta,
    const float* __restrict__ gam,
    float* __restrict__ Xre, float* __restrict__ Xim,
    uint32_t* __restrict__ PXre, uint32_t* __restrict__ PXim)
{
    const int n0 = blockIdx.x * 128;     // HID
    const int m0 = blockIdx.y * 128;     // BATCH
    const int z  = blockIdx.z;
    const uint32_t* __restrict__ Bmat = PB + (size_t)z * (NREC / 2) * HID;

    const int tid = threadIdx.x, warp = tid >> 5, lane = tid & 31;
    const int g = lane >> 2, t = lane & 3;
    const int wm = (warp >> 1) * 64, wn = (warp & 1) * 64;
    const int lm = lane >> 3;
    const int arow = wm + (lm & 1) * 8 + (lane & 7);
    const int acol = (lm >> 1) * 4;

    float acc[4][8][4];
    #pragma unroll
    for (int i = 0; i < 4; i++)
        #pragma unroll
        for (int j = 0; j < 8; j++)
            #pragma unroll
            for (int r = 0; r < 4; r++) acc[i][j][r] = 0.f;

    auto loadStage = [&](int s, int kt) {
        uint32_t* a = smem + s * ST;
        uint32_t* b = a + A_TILE;
        const int k2 = kt * 32;
        #pragma unroll
        for (int i = 0; i < 8; i++) {
            int c = tid + i * 128;
            int row = c >> 3, cc = (c & 7) * 4;
            cp16(a + row * SA + cc, PU + (size_t)(m0 + row) * (NREC / 2) + k2 + cc);
        }
        #pragma unroll
        for (int i = 0; i < 8; i++) {
            int c = tid + i * 128;
            int row = c >> 5, cc = (c & 31) * 4;
            cp16(b + row * SB + cc, Bmat + (size_t)(k2 + row) * HID + n0 + cc);
        }
    };

    const int NKT = (NREC / 2) / 32;   // 16
    loadStage(0, 0); cp_commit();
    loadStage(1, 1); cp_commit();

    for (int kt = 0; kt < NKT; kt++) {
        if (kt + 2 < NKT) cp_wait1(); else cp_wait0();
        __syncthreads();
        if (kt + 2 < NKT) { loadStage((kt + 2) % 3, kt + 2); cp_commit(); }

        const int s = kt % 3;
        const uint32_t* a = smem + s * ST;
        const uint32_t* b = a + A_TILE;
        const uint32_t aBase = s2u(a) + (uint32_t)((arow * SA + acol) << 2);
        #pragma unroll
        for (int ks = 0; ks < 4; ks++) KSTEP(ks);
    }

    // lambda/gamma tables for this block's 128 true H-columns
    float* sLr = (float*)smem;
    float* sLi = sLr + 128;
    float* sG  = sLr + 256;
    __syncthreads();
    if (tid < 128) {
        int h = n0 + tid;
        float e = expf(-expf(nu[h]));
        float th = theta[h];
        sLr[tid] = e * cosf(th);
        sLi[tid] = e * sinf(th);
        sG[tid]  = gam[h];
    }
    __syncthreads();

    float* __restrict__ Xout = z ? Xim : Xre;
    uint32_t* __restrict__ PXout = z ? PXim : PXre;
    #pragma unroll
    for (int i = 0; i < 4; i++) {
        int r0 = m0 + wm + i * 16 + g;
        #pragma unroll
        for (int j = 0; j < 8; j++) {
            int cl = wn + (j >> 2) * 32 + (j & 3) * 8 + 2 * t;
            float lr0 = sLr[cl],     li0 = sLi[cl],     g0 = sG[cl];
            float lr1 = sLr[cl + 1], li1 = sLi[cl + 1], g1 = sG[cl + 1];
            #pragma unroll
            for (int rr = 0; rr < 2; rr++) {
                int r = r0 + rr * 8;
                size_t off = (size_t)r * HID + n0 + cl;
                float2 sre = *(const float2*)(Sre + off);
                float2 sim = *(const float2*)(Sim + off);
                float t0 = acc[i][j][rr * 2 + 0], t1 = acc[i][j][rr * 2 + 1];
                float2 o;
                if (z == 0) {
                    o.x = sre.x * lr0 - sim.x * li0 + g0 * t0;
                    o.y = sre.y * lr1 - sim.y * li1 + g1 * t1;
                } else {
                    o.x = sre.x * li0 + sim.x * lr0 + g0 * t0;
                    o.y = sre.y * li1 + sim.y * lr1 + g1 * t1;
                }
                *(float2*)(Xout + off) = o;
                PXout[(size_t)r * (HID / 2) + (n0 + cl) / 2] = packh2(o.x, o.y);
            }
        }
    }
}

// =============================================================================
// GEMM2: Y = [Xre|Xim] @ [Cre;-Cim] + D*U   (K = 4096 halfs = 2048 u32)
// block 128x128, 128 thr, 4 warps, warp 64x64, 3 stages, 2 CTAs/SM
// =============================================================================
__global__ __launch_bounds__(128, 2) void lru_g2(
    const uint32_t* __restrict__ PXre, const uint32_t* __restrict__ PXim,
    const uint32_t* __restrict__ PC,
    const float* __restrict__ Dv,  const float* __restrict__ U,
    float* __restrict__ Y)
{
    const int n0 = blockIdx.x * 128;     // NREC
    const int m0 = blockIdx.y * 128;     // BATCH
    const int tid = threadIdx.x, warp = tid >> 5, lane = tid & 31;
    const int g = lane >> 2, t = lane & 3;
    const int wm = (warp >> 1) * 64, wn = (warp & 1) * 64;
    const int lm = lane >> 3;
    const int arow = wm + (lm & 1) * 8 + (lane & 7);
    const int acol = (lm >> 1) * 4;

    float acc[4][8][4];
    #pragma unroll
    for (int i = 0; i < 4; i++)
        #pragma unroll
        for (int j = 0; j < 8; j++)
            #pragma unroll
            for (int r = 0; r < 4; r++) acc[i][j][r] = 0.f;

    auto loadStage = [&](int s, int kt) {
        uint32_t* a = smem + s * ST;
        uint32_t* b = a + A_TILE;
        const int k2 = kt * 32;
        const uint32_t* Asrc = (k2 < HID / 2) ? PXre : PXim;
        const int ka = k2 & (HID / 2 - 1);
        #pragma unroll
        for (int i = 0; i < 8; i++) {
            int c = tid + i * 128;
            int row = c >> 3, cc = (c & 7) * 4;
            cp16(a + row * SA + cc, Asrc + (size_t)(m0 + row) * (HID / 2) + ka + cc);
        }
        #pragma unroll
        for (int i = 0; i < 8; i++) {
            int c = tid + i * 128;
            int row = c >> 5, cc = (c & 31) * 4;
            cp16(b + row * SB + cc, PC + (size_t)(k2 + row) * NREC + n0 + cc);
        }
    };

    const int NKT = 2048 / 32;    // 64
    loadStage(0, 0); cp_commit();
    loadStage(1, 1); cp_commit();

    for (int kt = 0; kt < NKT; kt++) {
        if (kt + 2 < NKT) cp_wait1(); else cp_wait0();
        __syncthreads();
        if (kt + 2 < NKT) { loadStage((kt + 2) % 3, kt + 2); cp_commit(); }

        const int s = kt % 3;
        const uint32_t* a = smem + s * ST;
        const uint32_t* b = a + A_TILE;
        const uint32_t aBase = s2u(a) + (uint32_t)((arow * SA + acol) << 2);
        #pragma unroll
        for (int ks = 0; ks < 4; ks++) KSTEP(ks);
    }

    #pragma unroll
    for (int i = 0; i < 4; i++) {
        int r0 = m0 + wm + i * 16 + g;
        #pragma unroll
        for (int j = 0; j < 8; j++) {
            int cl = wn + (j >> 2) * 32 + (j & 3) * 8 + 2 * t;
            int c  = n0 + cl;
            float d0 = Dv[c], d1 = Dv[c + 1];
            #pragma unroll
            for (int rr = 0; rr < 2; rr++) {
                int r = r0 + rr * 8;
                size_t off = (size_t)r * NREC + c;
                float2 u = *(const float2*)(U + off);
                float2 o;
                o.x = acc[i][j][rr * 2 + 0] + d0 * u.x;
                o.y = acc[i][j][rr * 2 + 1] + d1 * u.y;
                *(float2*)(Y + off) = o;
            }
        }
    }
}

// =============================================================================
extern "C" void kernel_launch(void* const* d_in, const int* in_sizes, int n_in,
                              void* d_out, int out_size)
{
    const float* U   = (const float*)d_in[0];
    const float* Sre = (const float*)d_in[1];
    const float* Sim = (const float*)d_in[2];
    const float* Bre = (const float*)d_in[3];
    const float* Bim = (const float*)d_in[4];
    const float* Cre = (const float*)d_in[5];
    const float* Cim = (const float*)d_in[6];
    const float* Dv  = (const float*)d_in[7];
    const float* nu  = (const float*)d_in[8];
    const float* th  = (const float*)d_in[9];
    const float* gm  = (const float*)d_in[10];

    float* Y   = (float*)d_out;
    float* Xre = Y + (size_t)BATCH * NREC;
    float* Xim = Xre + (size_t)BATCH * HID;

    uint32_t *PU, *PB, *PC, *PXre, *PXim;
    cudaGetSymbolAddress((void**)&PU, g_PU);
    cudaGetSymbolAddress((void**)&PB, g_PB);
    cudaGetSymbolAddress((void**)&PC, g_PC);
    cudaGetSymbolAddress((void**)&PXre, g_PXre);
    cudaGetSymbolAddress((void**)&PXim, g_PXim);

    dim3 gw((NREC / 2) * HID / 256, 4);
    prep_w<<<gw, 256>>>(Bre, Bim, Cre, Cim, PB, PC);
    prep_u<<<BATCH * (NREC / 2) / 256, 256>>>(U, PU);

    cudaFuncSetAttribute(lru_g1, cudaFuncAttributeMaxDynamicSharedMemorySize, SMEM_B);
    cudaFuncSetAttribute(lru_g2, cudaFuncAttributeMaxDynamicSharedMemorySize, SMEM_B);

    dim3 g1(HID / 128, BATCH / 128, 2);    // 16 x 64 x 2
    lru_g1<<<g1, 128, SMEM_B>>>(PU, PB, Sre, Sim, nu, th, gm, Xre, Xim, PXre, PXim);

    dim3 g2(NREC / 128, BATCH / 128);      // 8 x 64
    lru_g2<<<g2, 128, SMEM_B>>>(PXre, PXim, PC, Dv, U, Y);
}